// round 10
// baseline (speedup 1.0000x reference)
#include <cuda_runtime.h>
#include <cuda_bf16.h>

#define G_MAX    128
#define NCELL1D  16
#define NCELLS   (NCELL1D * NCELL1D)
#define CELL_W   64.0f          // power of 2: x*(1/64) is exact
#define PROP_WMAX 206.0f        // max proposal w/h (204.8) + rounding slack
#define NP_STATIC 220000
#define NP_PAD   (NP_STATIC + NCELLS * 32)

// ---- scratch (__device__ globals; no allocation) ----
__device__ int    g_count[NCELLS];
__device__ int    g_cursor[NCELLS];
__device__ int    g_base[NCELLS];
__device__ float4 g_sprops[NP_PAD];
__device__ int    g_sidx[NP_PAD];
__device__ int    g_scell[NP_PAD];
__device__ float4 g_cbox[NCELLS * G_MAX];
__device__ float2 g_cmeta[NCELLS * G_MAX];   // {area, label_as_float}
__device__ int    g_ccount[NCELLS];

__device__ __forceinline__ int cell_of(float x, float y)
{
    // multiply by exact power of two -> exact; trunc -> px1 >= cx*64 exactly
    int cx = (int)(x * (1.0f / CELL_W));
    int cy = (int)(y * (1.0f / CELL_W));
    cx = min(max(cx, 0), NCELL1D - 1);
    cy = min(max(cy, 0), NCELL1D - 1);
    return cy * NCELL1D + cx;
}

// K0: reset counters and invalidate all slots (graph replays must be stateless)
__global__ void k0_init(int npad)
{
    int i = blockIdx.x * 256 + threadIdx.x;
    if (i < NCELLS) { g_count[i] = 0; g_cursor[i] = 0; }
    if (i < npad)   { g_sidx[i] = -1; g_scell[i] = -1; }
}

// K1: histogram proposals into cells
__global__ void k1_count(const float4* __restrict__ props, int N)
{
    int n = blockIdx.x * 256 + threadIdx.x;
    if (n < N) {
        float4 p = props[n];
        atomicAdd(&g_count[cell_of(p.x, p.y)], 1);
    }
}

// K2: exclusive scan of 32-padded counts -> per-cell base offsets
__global__ void k2_scan()
{
    __shared__ int s[NCELLS];
    int t = threadIdx.x;
    int v = (g_count[t] + 31) & ~31;           // pad to warp granularity
    s[t] = v;
    __syncthreads();
    #pragma unroll
    for (int off = 1; off < NCELLS; off <<= 1) {
        int add = (t >= off) ? s[t - off] : 0;
        __syncthreads();
        s[t] += add;
        __syncthreads();
    }
    g_base[t] = s[t] - v;                      // exclusive prefix
}

// K3: per-cell conservative candidate lists (order-preserving -> argmax tie
// order preserved). A gt is a candidate iff it COULD overlap some proposal
// whose (x1,y1) lies in this cell; every gt with inter > 0 is included, every
// excluded gt has inter == 0 exactly for all proposals of the cell.
__global__ void k3_cands(const float4* __restrict__ gt,
                         const int*    __restrict__ gtl32, int G)
{
    __shared__ int wcnt[4];
    const int b  = blockIdx.x;                  // cell id
    const int t  = threadIdx.x;                 // 0..127
    const int w  = t >> 5, lane = t & 31;

    const float xlo = (float)(b % NCELL1D) * CELL_W;
    const float ylo = (float)(b / NCELL1D) * CELL_W;
    const float xhi = xlo + CELL_W + PROP_WMAX; // px2 < xlo+64+204.8+slack
    const float yhi = ylo + CELL_W + PROP_WMAX;

    bool cand = false;
    float4 gb = make_float4(0.f, 0.f, 0.f, 0.f);
    if (t < G) {
        gb = gt[t];
        cand = (gb.x < xhi) && (gb.z > xlo) && (gb.y < yhi) && (gb.w > ylo);
    }
    unsigned bal = __ballot_sync(0xffffffffu, cand);
    if (lane == 0) wcnt[w] = __popc(bal);
    __syncthreads();
    int base = 0;
    #pragma unroll
    for (int k = 0; k < 4; ++k) if (k < w) base += wcnt[k];
    if (cand) {
        int pos = base + __popc(bal & ((1u << lane) - 1u));
        g_cbox[b * G_MAX + pos] = gb;
        float area = __fmul_rn(__fsub_rn(gb.z, gb.x), __fsub_rn(gb.w, gb.y));
        // labels >= 1, so little-endian i64 => word 1 (hi of elem 0) == 0
        int is64 = (gtl32[1] == 0) ? 1 : 0;
        float labf = (float)gtl32[is64 ? (2 * t) : t];
        g_cmeta[b * G_MAX + pos] = make_float2(area, labf);
    }
    if (t == 0) g_ccount[b] = wcnt[0] + wcnt[1] + wcnt[2] + wcnt[3];
}

// K4: scatter proposals into cell-sorted, warp-aligned slots. Slot assignment
// order is nondeterministic (atomics) but the per-proposal result depends only
// on its own data + its cell's list, and output is written at the original
// index -> final output deterministic.
__global__ void k4_scatter(const float4* __restrict__ props, int N)
{
    int n = blockIdx.x * 256 + threadIdx.x;
    if (n < N) {
        float4 p = props[n];
        int c = cell_of(p.x, p.y);
        int s = g_base[c] + atomicAdd(&g_cursor[c], 1);
        g_sprops[s] = p;
        g_sidx[s]   = n;
        g_scell[s]  = c;
    }
}

// K5: main. Each warp's active lanes share one cell (bases are 32-aligned),
// so the candidate loop is warp-uniform with broadcast LDG.
__global__ __launch_bounds__(256)
void k5_main(const float4* __restrict__ gt,
             const int*    __restrict__ gtl32,
             float*        __restrict__ out_labels,
             float4*       __restrict__ out_boxes,
             int npad)
{
    int slot = blockIdx.x * 256 + threadIdx.x;
    if (slot >= npad) return;

    const int cell = g_scell[slot];
    const float4 p = g_sprops[slot];        // garbage if cell < 0 (never used)
    const int cnt  = (cell >= 0) ? g_ccount[cell] : 0;
    const float4* __restrict__ cb = &g_cbox[(cell >= 0 ? cell : 0) * G_MAX];
    const float2* __restrict__ cm = &g_cmeta[(cell >= 0 ? cell : 0) * G_MAX];

    const float parea = __fmul_rn(__fsub_rn(p.z, p.x), __fsub_rn(p.w, p.y));

    // Sentinel: bestI=0,bestS=1 -> only inter>0 can win; all-zero row keeps
    // bestC=-1 -> gt[0]/label[0], matching jnp.argmax-of-zeros.
    float bestI = 0.0f, bestS = 1.0f;
    int bestC = -1;

    #pragma unroll 4
    for (int i = 0; i < cnt; ++i) {
        const float4 gb = cb[i];             // warp-uniform -> broadcast
        const float2 mt = cm[i];
        float x1 = fmaxf(gb.x, p.x);
        float y1 = fmaxf(gb.y, p.y);
        float x2 = fminf(gb.z, p.z);
        float y2 = fminf(gb.w, p.w);
        float dx = fmaxf(__fsub_rn(x2, x1), 0.0f);
        float dy = fmaxf(__fsub_rn(y2, y1), 0.0f);
        float inter = __fmul_rn(dx, dy);
        float S     = __fadd_rn(mt.x, parea);       // area_g + parea
        // iou = inter/(S-inter) monotone in inter/S (S > 0):
        //   i1/(S1-i1) > i2/(S2-i2) <=> i1*S2 > i2*S1 (cross terms cancel).
        // FFMA sign of the cross-difference; strict > keeps the earlier
        // candidate (ascending g) -> jnp.argmax first-max semantics.
        float d = __fmaf_rn(inter, bestS, -__fmul_rn(bestI, S));
        bool take = d > 0.0f;
        bestI = take ? inter : bestI;
        bestS = take ? S     : bestS;
        bestC = take ? i     : bestC;
    }

    const int orig = g_sidx[slot];
    if (orig >= 0) {
        float4 obox;
        float lab;
        if (bestC >= 0) {
            obox = cb[bestC];
            lab  = cm[bestC].y;
        } else {
            obox = gt[0];
            lab  = (float)gtl32[0];   // low word == label[0] for i32 and i64
        }
        // uni = fl(bestS-bestI) == reference's fl(fl(a1+a2)-inter);
        // single IEEE division -> bitwise-equal iou for the winning pair.
        float uni = __fsub_rn(bestS, bestI);
        float iou = __fdiv_rn(bestI, uni);
        if (iou < 0.5f) lab = (iou >= 0.1f) ? 0.0f : -1.0f;
        if (out_labels) out_labels[orig] = lab;
        if (out_boxes)  out_boxes[orig]  = obox;
    }
}

// ---- fallback: proven dense kernel (R4), used if shapes exceed scratch ----
__global__ __launch_bounds__(256)
void roi_dense_kernel(const float4* __restrict__ props,
                      const float4* __restrict__ gt,
                      const int*    __restrict__ gtl32,
                      float*        __restrict__ out_labels,
                      float4*       __restrict__ out_boxes,
                      int N, int G)
{
    __shared__ float4 s_gt[G_MAX];
    __shared__ float  s_area[G_MAX];
    __shared__ float  s_lab[G_MAX];
    const int t = threadIdx.x;
    if (t < G && t < G_MAX) {
        float4 b = gt[t];
        s_gt[t]   = b;
        s_area[t] = __fmul_rn(__fsub_rn(b.z, b.x), __fsub_rn(b.w, b.y));
        int is64 = (gtl32[1] == 0) ? 1 : 0;
        s_lab[t] = (float)gtl32[is64 ? (2 * t) : t];
    }
    __syncthreads();
    const int n  = blockIdx.x * 256 + t;
    const int ni = (n < N) ? n : (N - 1);
    const float4 p = props[ni];
    const float parea = __fmul_rn(__fsub_rn(p.z, p.x), __fsub_rn(p.w, p.y));
    float bestI = 0.0f, bestS = 1.0f;
    int bestIdx = 0;
    for (int g = 0; g < G; ++g) {
        const float4 gb = s_gt[g];
        float x1 = fmaxf(gb.x, p.x), y1 = fmaxf(gb.y, p.y);
        float x2 = fminf(gb.z, p.z), y2 = fminf(gb.w, p.w);
        float dx = fmaxf(__fsub_rn(x2, x1), 0.0f);
        float dy = fmaxf(__fsub_rn(y2, y1), 0.0f);
        float inter = __fmul_rn(dx, dy);
        float S     = __fadd_rn(s_area[g], parea);
        float d = __fmaf_rn(inter, bestS, -__fmul_rn(bestI, S));
        bool take = d > 0.0f;
        bestI = take ? inter : bestI;
        bestS = take ? S : bestS;
        bestIdx = take ? g : bestIdx;
    }
    if (n < N) {
        float uni = __fsub_rn(bestS, bestI);
        float iou = __fdiv_rn(bestI, uni);
        float lab = s_lab[bestIdx];
        if (iou < 0.5f) lab = (iou >= 0.1f) ? 0.0f : -1.0f;
        if (out_labels) out_labels[n] = lab;
        if (out_boxes)  out_boxes[n]  = s_gt[bestIdx];
    }
}

extern "C" void kernel_launch(void* const* d_in, const int* in_sizes, int n_in,
                              void* d_out, int out_size)
{
    const float4* props = (const float4*)d_in[0];
    const float4* gt    = (const float4*)d_in[1];
    const int*    gtl   = (const int*)d_in[2];

    const int N = in_sizes[0] / 4;
    const int G = in_sizes[1] / 4;

    float*  out       = (float*)d_out;
    float*  out_label = nullptr;
    float4* out_boxes = nullptr;
    if (out_size == 5 * N) {
        out_label = out;
        out_boxes = (float4*)(out + N);
    } else if (out_size == 4 * N) {
        out_boxes = (float4*)out;
    } else {
        out_label = out;
    }

    if (N > NP_STATIC || G > G_MAX || G < 2) {
        roi_dense_kernel<<<(N + 255) / 256, 256>>>(props, gt, gtl,
                                                   out_label, out_boxes, N, G);
        return;
    }

    const int npad  = N + NCELLS * 32;           // upper bound on padded total
    const int gP    = (N + 255) / 256;
    const int gPad  = (npad + 255) / 256;
    const int gInit = (max(npad, NCELLS) + 255) / 256;

    k0_init   <<<gInit, 256>>>(npad);
    k1_count  <<<gP, 256>>>(props, N);
    k2_scan   <<<1, NCELLS>>>();
    k3_cands  <<<NCELLS, 128>>>(gt, gtl, G);
    k4_scatter<<<gP, 256>>>(props, N);
    k5_main   <<<gPad, 256>>>(gt, gtl, out_label, out_boxes, npad);
}

// round 11
// speedup vs baseline: 5.3989x; 5.3989x over previous
#include <cuda_runtime.h>
#include <cuda_bf16.h>

#define G_MAX 128
#define BLOCK 256

// Lane pairs (2k, 2k+1) share one proposal: even lane scans g in [0, G/2),
// odd lane scans [G/2, G); merged with one shfl + exact compare.
__global__ __launch_bounds__(BLOCK)
void roi_match_kernel(const float4* __restrict__ props,
                      const float4* __restrict__ gt,
                      const int*    __restrict__ gtl32,   // gt labels, i32 or i64 (auto-detect)
                      float*        __restrict__ out_labels,
                      float4*       __restrict__ out_boxes,
                      int N, int G)
{
    __shared__ float4 s_gt[G_MAX];
    __shared__ float4 s_areav[G_MAX / 4];   // areas batched 4-wide
    __shared__ float  s_lab[G_MAX];

    const int t = threadIdx.x;
    if (t < G) {
        float4 b = gt[t];
        s_gt[t] = b;
        ((float*)s_areav)[t] = __fmul_rn(__fsub_rn(b.z, b.x), __fsub_rn(b.w, b.y));
        // labels >= 1, so little-endian i64 => word 1 (hi word of elem 0) == 0
        int is64 = (gtl32[1] == 0) ? 1 : 0;
        s_lab[t] = (float)gtl32[is64 ? (2 * t) : t];
    }
    __syncthreads();

    const int half = t & 1;
    const int n    = blockIdx.x * (BLOCK / 2) + (t >> 1);
    const int ni   = (n < N) ? n : (N - 1);          // clamp tail loads; store guarded

    const float4 p = props[ni];
    const float parea = __fmul_rn(__fsub_rn(p.z, p.x), __fsub_rn(p.w, p.y));

    // Sentinel (bestI=0, bestS=1): only strictly-positive inter can win; an
    // all-zero row resolves to idx 0, iou = 0/(1-0) = 0 -> label -1, box gt[0],
    // matching jnp.argmax-of-zeros.
    float bestI = 0.0f, bestS = 1.0f;
    const int gs = half * (G >> 1);
    int bestIdx = gs;

    // G/2 assumed multiple of 4 here (G % 8 == 0; checked on host).
    #pragma unroll 2
    for (int q = 0; q < (G >> 3); ++q) {             // 4 gts per chunk, 2 chunks/iter
        const int g0 = gs + q * 4;
        const float4 av = s_areav[g0 >> 2];          // one LDS.128 per 4 areas
        const float areas[4] = { av.x, av.y, av.z, av.w };
        #pragma unroll
        for (int k = 0; k < 4; ++k) {
            const int g = g0 + k;
            const float4 gb = s_gt[g];               // broadcast LDS.128
            float x1 = fmaxf(gb.x, p.x);
            float y1 = fmaxf(gb.y, p.y);
            float x2 = fminf(gb.z, p.z);
            float y2 = fminf(gb.w, p.w);
            float dx = fmaxf(__fsub_rn(x2, x1), 0.0f);
            float dy = __fsub_rn(y2, y1);            // UNclamped (see proof)
            // inter' = max(dx,0)*dy. If dy<0: inter' <= 0 so d <= 0 -> never
            // taken (bestI>=0, S>0; at sentinel fl(neg*1) < 0). If taken,
            // inter' > 0 forces dy > 0, so inter' == reference's clamped inter
            // bitwise. Saves one FMNMX on the alu pipe.
            float inter = __fmul_rn(dx, dy);
            float S     = __fadd_rn(areas[k], parea);    // area_g + parea
            // iou = inter/(S - inter) monotone in inter/S (S > 0):
            //   i1/(S1-i1) > i2/(S2-i2)  <=>  i1*S2 > i2*S1  (cross terms cancel)
            // FFMA sign of the cross-difference (~1 ulp of exact); strict >
            // keeps the earlier index (jnp.argmax first-max semantics).
            float d = __fmaf_rn(inter, bestS, -__fmul_rn(bestI, S));
            bool take = d > 0.0f;
            bestI   = take ? inter : bestI;
            bestS   = take ? S     : bestS;
            bestIdx = take ? g     : bestIdx;
        }
    }

    // Pair merge: take partner iff strictly greater; the even lane holds the
    // lower g range, so ties keep the smaller index. Even lane stores.
    float oI   = __shfl_xor_sync(0xffffffffu, bestI, 1);
    float oS   = __shfl_xor_sync(0xffffffffu, bestS, 1);
    int   oIdx = __shfl_xor_sync(0xffffffffu, bestIdx, 1);
    float dm = __fmaf_rn(oI, bestS, -__fmul_rn(bestI, oS));
    if (dm > 0.0f) { bestI = oI; bestS = oS; bestIdx = oIdx; }

    if (half == 0 && n < N) {
        // uni = fl(bestS - bestI) == reference's fl(fl(a1+a2) - inter);
        // single IEEE division -> bitwise-equal iou for the winning pair.
        float uni = __fsub_rn(bestS, bestI);
        float iou = __fdiv_rn(bestI, uni);
        float lab = s_lab[bestIdx];
        if (iou < 0.5f) lab = (iou >= 0.1f) ? 0.0f : -1.0f;
        if (out_labels) out_labels[n] = lab;
        if (out_boxes)  out_boxes[n]  = s_gt[bestIdx];
    }
}

// Generic fallback (R4 logic) for shapes the fast path doesn't cover.
__global__ __launch_bounds__(256)
void roi_dense_kernel(const float4* __restrict__ props,
                      const float4* __restrict__ gt,
                      const int*    __restrict__ gtl32,
                      float*        __restrict__ out_labels,
                      float4*       __restrict__ out_boxes,
                      int N, int G)
{
    __shared__ float4 s_gt[G_MAX];
    __shared__ float  s_area[G_MAX];
    __shared__ float  s_lab[G_MAX];
    const int t = threadIdx.x;
    if (t < G && t < G_MAX) {
        float4 b = gt[t];
        s_gt[t]   = b;
        s_area[t] = __fmul_rn(__fsub_rn(b.z, b.x), __fsub_rn(b.w, b.y));
        int is64 = (G >= 2 && gtl32[1] == 0) ? 1 : 0;
        s_lab[t] = (float)gtl32[is64 ? (2 * t) : t];
    }
    __syncthreads();
    const int n  = blockIdx.x * 256 + t;
    const int ni = (n < N) ? n : (N - 1);
    const float4 p = props[ni];
    const float parea = __fmul_rn(__fsub_rn(p.z, p.x), __fsub_rn(p.w, p.y));
    float bestI = 0.0f, bestS = 1.0f;
    int bestIdx = 0;
    for (int g = 0; g < G; ++g) {
        const float4 gb = s_gt[g];
        float x1 = fmaxf(gb.x, p.x), y1 = fmaxf(gb.y, p.y);
        float x2 = fminf(gb.z, p.z), y2 = fminf(gb.w, p.w);
        float dx = fmaxf(__fsub_rn(x2, x1), 0.0f);
        float dy = fmaxf(__fsub_rn(y2, y1), 0.0f);
        float inter = __fmul_rn(dx, dy);
        float S     = __fadd_rn(s_area[g], parea);
        float d = __fmaf_rn(inter, bestS, -__fmul_rn(bestI, S));
        bool take = d > 0.0f;
        bestI = take ? inter : bestI;
        bestS = take ? S : bestS;
        bestIdx = take ? g : bestIdx;
    }
    if (n < N) {
        float uni = __fsub_rn(bestS, bestI);
        float iou = __fdiv_rn(bestI, uni);
        float lab = s_lab[bestIdx];
        if (iou < 0.5f) lab = (iou >= 0.1f) ? 0.0f : -1.0f;
        if (out_labels) out_labels[n] = lab;
        if (out_boxes)  out_boxes[n]  = s_gt[bestIdx];
    }
}

extern "C" void kernel_launch(void* const* d_in, const int* in_sizes, int n_in,
                              void* d_out, int out_size)
{
    const float4* props = (const float4*)d_in[0];
    const float4* gt    = (const float4*)d_in[1];
    const int*    gtl   = (const int*)d_in[2];

    const int N = in_sizes[0] / 4;
    const int G = in_sizes[1] / 4;

    float*  out       = (float*)d_out;
    float*  out_label = nullptr;
    float4* out_boxes = nullptr;
    if (out_size == 5 * N) {            // [labels (N) ; boxes (4N)] as f32
        out_label = out;
        out_boxes = (float4*)(out + N); // 16B-aligned since N % 4 == 0
    } else if (out_size == 4 * N) {     // boxes only
        out_boxes = (float4*)out;
    } else {                            // labels only
        out_label = out;
    }

    if (G <= G_MAX && G >= 8 && (G % 8) == 0) {
        const int props_per_block = BLOCK / 2;
        const int grid = (N + props_per_block - 1) / props_per_block;
        roi_match_kernel<<<grid, BLOCK>>>(props, gt, gtl, out_label, out_boxes, N, G);
    } else {
        roi_dense_kernel<<<(N + 255) / 256, 256>>>(props, gt, gtl,
                                                   out_label, out_boxes, N, G);
    }
}